// round 11
// baseline (speedup 1.0000x reference)
#include <cuda_runtime.h>
#include <cuda_fp16.h>
#include <cstdint>

#define BB 128
#define HH 1024
#define LL 256
#define NN 64

// Scratch (device globals: no allocations allowed)
__device__ float  g_k[HH * LL];                       // 1 MB  : S4D conv kernel (H,L) fp32
__device__ __half g_Wh[2 * HH * HH];                  // 4 MB  : W_out fp16
__device__ __half g_xh[(size_t)BB * HH * LL];         // 64 MB : x in fp16 [b][h][l]
__device__ __half g_yh[(size_t)BB * HH * LL];         // 64 MB : post-gelu activations fp16 [b][h][l]
__device__ __half g_T[(size_t)HH * LL * LL];          // 134 MB: Toeplitz T[h][s][l] = k_h[l-s]

// ---------------------------------------------------------------------------
// helpers
// ---------------------------------------------------------------------------
__device__ __forceinline__ float gelu_tanh(float v) {
    float t = tanhf(0.7978845608028654f * (v + 0.044715f * v * v * v));
    return 0.5f * v * (1.0f + t);
}
__device__ __forceinline__ uint32_t smem_u32(const void* p) {
    return (uint32_t)__cvta_generic_to_shared(p);
}
__device__ __forceinline__ void cp_async16(uint32_t dst, const void* src) {
    asm volatile("cp.async.cg.shared.global [%0], [%1], 16;\n" :: "r"(dst), "l"(src));
}
__device__ __forceinline__ void cp_commit() { asm volatile("cp.async.commit_group;\n"); }
__device__ __forceinline__ void cp_wait0() { asm volatile("cp.async.wait_group 0;\n"); }
__device__ __forceinline__ void cp_wait1() { asm volatile("cp.async.wait_group 1;\n"); }
__device__ __forceinline__ void cp_wait2() { asm volatile("cp.async.wait_group 2;\n"); }

__device__ __forceinline__ void mma_f16(float c[4], const uint32_t a[4],
                                        uint32_t b0, uint32_t b1) {
    asm volatile(
        "mma.sync.aligned.m16n8k16.row.col.f32.f16.f16.f32 "
        "{%0,%1,%2,%3}, {%4,%5,%6,%7}, {%8,%9}, {%0,%1,%2,%3};"
        : "+f"(c[0]), "+f"(c[1]), "+f"(c[2]), "+f"(c[3])
        : "r"(a[0]), "r"(a[1]), "r"(a[2]), "r"(a[3]), "r"(b0), "r"(b1));
}

#define LDM_X4(r0, r1, r2, r3, addr) \
    asm volatile("ldmatrix.sync.aligned.m8n8.x4.shared.b16 {%0,%1,%2,%3}, [%4];" \
                 : "=r"(r0), "=r"(r1), "=r"(r2), "=r"(r3) : "r"(addr))
#define LDM_X4T(r0, r1, r2, r3, addr) \
    asm volatile("ldmatrix.sync.aligned.m8n8.x4.trans.shared.b16 {%0,%1,%2,%3}, [%4];" \
                 : "=r"(r0), "=r"(r1), "=r"(r2), "=r"(r3) : "r"(addr))

// ---------------------------------------------------------------------------
// Kernel 1: S4D kernel materialization (fp32 k)
// ---------------------------------------------------------------------------
__global__ __launch_bounds__(256) void k_kernel(
    const float* __restrict__ log_dt, const float* __restrict__ A_real_log,
    const float* __restrict__ A_imag, const float* __restrict__ C_re,
    const float* __restrict__ C_im) {
    int h = blockIdx.x;
    __shared__ float sCr[NN], sCi[NN], sAr[NN], sAi[NN];
    int tid = threadIdx.x;
    if (tid < NN) {
        float dt = expf(log_dt[h]);
        float Ar = -expf(A_real_log[h * NN + tid]);
        float Ai = A_imag[h * NN + tid];
        float dAr = Ar * dt, dAi = Ai * dt;
        float er = expf(dAr), sv, cv;
        sincosf(dAi, &sv, &cv);
        float Exr = er * cv - 1.0f;
        float Exi = er * sv;
        float cr = C_re[h * NN + tid], ci = C_im[h * NN + tid];
        float nr = cr * Exr - ci * Exi;
        float ni = cr * Exi + ci * Exr;
        float den = 1.0f / (Ar * Ar + Ai * Ai);
        sCr[tid] = (nr * Ar + ni * Ai) * den;
        sCi[tid] = (ni * Ar - nr * Ai) * den;
        sAr[tid] = dAr;
        sAi[tid] = dAi;
    }
    __syncthreads();
    float l = (float)tid;
    float acc = 0.0f;
#pragma unroll 4
    for (int n = 0; n < NN; n++) {
        float mag = expf(sAr[n] * l);
        float sv, cv;
        sincosf(sAi[n] * l, &sv, &cv);
        acc += sCr[n] * (mag * cv) - sCi[n] * (mag * sv);
    }
    g_k[h * LL + tid] = 2.0f * acc;
}

// ---------------------------------------------------------------------------
// Kernel 2: fp16-cast W (row-major)
// ---------------------------------------------------------------------------
__global__ __launch_bounds__(256) void wprep_kernel(const float* __restrict__ W) {
    int i = (blockIdx.x * 256 + threadIdx.x) * 4;
    if (i >= 2 * HH * HH) return;
    float4 v = *(const float4*)&W[i];
    union { __half2 h[2]; uint2 u; } c;
    c.h[0] = __floats2half2_rn(v.x, v.y);
    c.h[1] = __floats2half2_rn(v.z, v.w);
    *(uint2*)&g_Wh[i] = c.u;
}

// ---------------------------------------------------------------------------
// Kernel 2b: fp16-cast x
// ---------------------------------------------------------------------------
__global__ __launch_bounds__(256) void xprep_kernel(const float* __restrict__ x) {
    size_t i = ((size_t)blockIdx.x * 256 + threadIdx.x) * 4;
    float4 v = *(const float4*)&x[i];
    union { __half2 h[2]; uint2 u; } c;
    c.h[0] = __floats2half2_rn(v.x, v.y);
    c.h[1] = __floats2half2_rn(v.z, v.w);
    *(uint2*)&g_xh[i] = c.u;
}

// ---------------------------------------------------------------------------
// Kernel 2c: Toeplitz materialization T[h][s][l] = k_h[l-s] (l>=s else 0).
// One block per head; coalesced 16B stores.
// ---------------------------------------------------------------------------
__global__ __launch_bounds__(256) void tprep_kernel() {
    __shared__ __half kh[256];
    int h = blockIdx.x;
    int tid = threadIdx.x;
    kh[tid] = __float2half(g_k[(size_t)h * LL + tid]);
    __syncthreads();
    __half* Th = g_T + (size_t)h * LL * LL;
#pragma unroll 4
    for (int idx = tid; idx < 256 * 32; idx += 256) {
        int s = idx >> 5;
        int l0 = (idx & 31) * 8;
        union { __half hv[8]; uint4 u; } pk;
#pragma unroll
        for (int j = 0; j < 8; j++) {
            int l = l0 + j;
            pk.hv[j] = (l >= s) ? kh[l - s] : __half(0.0f);
        }
        *(uint4*)&Th[(size_t)s * LL + l0] = pk.u;
    }
}

// ---------------------------------------------------------------------------
// Kernel 3: conv as per-head Toeplitz GEMM (tensor cores), T from gmem.
// Y[b][l] = sum_s X[b][s] * T[s][l]
// Block = (mb in 0..1, head h): M=64 batches, N=256 l, K=256 s in 16 chunks.
// 8 warps = 2(m) x 4(n); warp tile m32 x n64. X and T both via cp.async,
// double-buffered. Causal skip on MMAs (wn*64+63 >= k0).
// Epilogue: + D*x, gelu, fp16 store. mma rows are BATCHES (stride HH*LL).
// ---------------------------------------------------------------------------
#define XP 24          // X tile pitch (halfs)
#define TP 264         // T tile pitch (halfs)

__global__ __launch_bounds__(256) void convgemm_kernel(const float* __restrict__ D) {
    __shared__ __align__(16) __half Xs[2][64 * XP];     // 6144 B
    __shared__ __align__(16) __half Ts[2][16 * TP];     // 16896 B

    int mb = blockIdx.x;            // 0..1 (64 batches each)
    int h  = blockIdx.y;
    int tid = threadIdx.x;
    int lane = tid & 31;
    int wid = tid >> 5;
    int wm = wid & 1;               // m: 32 rows
    int wn = wid >> 1;              // n: 64 cols

    float acc[2][8][4];
#pragma unroll
    for (int mi = 0; mi < 2; mi++)
#pragma unroll
        for (int t = 0; t < 8; t++)
#pragma unroll
            for (int r = 0; r < 4; r++) acc[mi][t][r] = 0.0f;

    // X staging: threads 0..127 -> (row, seg)
    int xr = tid >> 1, xseg = tid & 1;
    const __half* xS = g_xh + ((size_t)(mb * 64 + xr) * HH + h) * LL + xseg * 8;  // += 16/chunk
    uint32_t xD[2] = { smem_u32(&Xs[0][xr * XP + xseg * 8]),
                       smem_u32(&Xs[1][xr * XP + xseg * 8]) };

    // T staging: tasks tid and tid+256; task τ: row=τ>>5 (0..15), seg=τ&31
    int tr0 = tid >> 5, tseg = tid & 31;
    const __half* tS = g_T + (size_t)h * LL * LL + (size_t)tr0 * LL + tseg * 8;   // += 16*LL/chunk
    uint32_t tD0[2] = { smem_u32(&Ts[0][tr0 * TP + tseg * 8]),
                        smem_u32(&Ts[1][tr0 * TP + tseg * 8]) };
    uint32_t tD1[2] = { smem_u32(&Ts[0][(tr0 + 8) * TP + tseg * 8]),
                        smem_u32(&Ts[1][(tr0 + 8) * TP + tseg * 8]) };
    const size_t TROW8 = (size_t)8 * LL;

    // fragment addresses
    int lm = lane & 15, lh = lane >> 4;
    uint32_t xAddr[2] = { smem_u32(&Xs[0][(wm * 32 + lm) * XP + lh * 8]),
                          smem_u32(&Xs[1][(wm * 32 + lm) * XP + lh * 8]) };
    uint32_t tAddr[2] = { smem_u32(&Ts[0][lm * TP + wn * 64 + lh * 8]),
                          smem_u32(&Ts[1][lm * TP + wn * 64 + lh * 8]) };

#define STAGE_CONV(buf) do { \
        if (tid < 128) cp_async16(xD[buf], xS); \
        cp_async16(tD0[buf], tS); \
        cp_async16(tD1[buf], tS + TROW8); \
        cp_commit(); xS += 16; tS += 16 * LL; } while (0)

#define CONV_COMPUTE(buf, k0) do { \
        if (wn * 64 + 63 >= (k0)) { \
            uint32_t aa0[4], aa1[4]; \
            LDM_X4(aa0[0], aa0[1], aa0[2], aa0[3], xAddr[buf]); \
            LDM_X4(aa1[0], aa1[1], aa1[2], aa1[3], xAddr[buf] + 16 * XP * 2); \
            _Pragma("unroll") \
            for (int p = 0; p < 4; p++) { \
                if (wn * 64 + p * 16 + 15 >= (k0)) { \
                    uint32_t b0, b1, b2, b3; \
                    LDM_X4T(b0, b1, b2, b3, tAddr[buf] + p * 32); \
                    mma_f16(acc[0][2 * p],     aa0, b0, b1); \
                    mma_f16(acc[0][2 * p + 1], aa0, b2, b3); \
                    mma_f16(acc[1][2 * p],     aa1, b0, b1); \
                    mma_f16(acc[1][2 * p + 1], aa1, b2, b3); \
                } \
            } \
        } } while (0)

    // prologue: chunk 0 -> buf0
    STAGE_CONV(0);
    cp_wait0();
    __syncthreads();

#pragma unroll 1
    for (int c = 0; c < 16; c++) {
        int cur = c & 1, nxt = cur ^ 1;
        if (c < 15) STAGE_CONV(nxt);
        CONV_COMPUTE(cur, c * 16);
        if (c < 15) cp_wait0();
        __syncthreads();
    }

    // epilogue: + D*x, gelu, store fp16.  batch stride = HH*LL!
    float Dv = D[h];
    int r = lane >> 2;
    int c2 = (lane & 3) << 1;
    const size_t BSTRIDE8 = (size_t)8 * HH * LL;
#pragma unroll
    for (int mi = 0; mi < 2; mi++) {
        int row0 = mb * 64 + wm * 32 + mi * 16 + r;      // batch index
#pragma unroll
        for (int t = 0; t < 8; t++) {
            int l = wn * 64 + t * 8 + c2;
            size_t a0 = ((size_t)row0 * HH + h) * LL + l;
            size_t a8 = a0 + BSTRIDE8;                   // batch row0+8
            __half2 x0 = *(const __half2*)&g_xh[a0];
            __half2 x8 = *(const __half2*)&g_xh[a8];
            float y0 = gelu_tanh(acc[mi][t][0] + Dv * __low2float(x0));
            float y1 = gelu_tanh(acc[mi][t][1] + Dv * __high2float(x0));
            float y2 = gelu_tanh(acc[mi][t][2] + Dv * __low2float(x8));
            float y3 = gelu_tanh(acc[mi][t][3] + Dv * __high2float(x8));
            *(__half2*)&g_yh[a0] = __floats2half2_rn(y0, y1);
            *(__half2*)&g_yh[a8] = __floats2half2_rn(y2, y3);
        }
    }
}

// ---------------------------------------------------------------------------
// Kernel 4: fp16 GEMM + GLU (mma.sync m16n8k16 + ldmatrix), 4-stage cp.async
// pipeline with wait_group 2 (one barrier per k32 chunk).
// Block: 64 h-out (both GLU halves) x 128 l; 8 warps = 4(m) x 2(n).
// ---------------------------------------------------------------------------
#define AP 40
#define BP 136
#define A_H (128 * AP)                 // 5120 halfs
#define B_H (32 * BP)                  // 4352 halfs
#define ST_H (A_H + B_H)               // 9472 halfs
#define ST_B (ST_H * 2)                // 18944 B / stage
#define GEMM_SMEM_BYTES (4 * ST_B)     // 75776 B

__global__ __launch_bounds__(256, 2) void gemm_glu_kernel(const float* __restrict__ bias,
                                                          float* __restrict__ out) {
    extern __shared__ __half smh[];

    int lblk = blockIdx.x;
    int hb   = blockIdx.y;
    int b    = blockIdx.z;
    int tid = threadIdx.x;
    int lane = tid & 31;
    int wid = tid >> 5;
    int wm = wid & 3;
    int wn = wid >> 2;

    float ca[8][4], cb[8][4];
#pragma unroll
    for (int t = 0; t < 8; t++)
#pragma unroll
        for (int r = 0; r < 4; r++) { ca[t][r] = 0.0f; cb[t][r] = 0.0f; }

    // staging descriptors
    int arow = tid >> 1, aseg2 = (tid & 1) * 2;
    int wrow = (arow < 64) ? (hb * 64 + arow) : (960 + hb * 64 + arow);
    const __half* aS = g_Wh + (size_t)wrow * HH + aseg2 * 8;
    uint32_t aD = smem_u32(smh + arow * AP + aseg2 * 8);

    int brow = tid >> 3, bs2 = (tid & 7) * 2;
    const __half* bS = g_yh + (size_t)b * HH * LL + (size_t)brow * LL + lblk * 128 + bs2 * 8;
    uint32_t bD = smem_u32(smh + A_H + brow * BP + bs2 * 8);

#define STAGE(off) do { \
        cp_async16(aD + (off), aS); cp_async16(aD + (off) + 16, aS + 8); \
        cp_async16(bD + (off), bS); cp_async16(bD + (off) + 16, bS + 8); \
        cp_commit(); aS += 32; bS += 32 * LL; } while (0)

    int lm = lane & 15, lh = lane >> 4;
    uint32_t aAddrA = smem_u32(smh + (wm * 16 + lm) * AP + lh * 8);
    uint32_t aAddrB = aAddrA + 64 * AP * 2;
    uint32_t bAddr  = smem_u32(smh + A_H + lm * BP + wn * 64 + lh * 8);

#define COMPUTE(off) do { \
        _Pragma("unroll") \
        for (int s = 0; s < 2; s++) { \
            uint32_t aa[4], ab[4]; \
            LDM_X4(aa[0], aa[1], aa[2], aa[3], aAddrA + (off) + s * 32); \
            LDM_X4(ab[0], ab[1], ab[2], ab[3], aAddrB + (off) + s * 32); \
            _Pragma("unroll") \
            for (int p = 0; p < 4; p++) { \
                uint32_t b0, b1, b2, b3; \
                LDM_X4T(b0, b1, b2, b3, bAddr + (off) + s * (16 * BP * 2) + p * 32); \
                mma_f16(ca[2 * p],     aa, b0, b1); \
                mma_f16(ca[2 * p + 1], aa, b2, b3); \
                mma_f16(cb[2 * p],     ab, b0, b1); \
                mma_f16(cb[2 * p + 1], ab, b2, b3); \
            } \
        } } while (0)

    // 4-stage pipeline over 32 chunks
    STAGE(0);
    STAGE(ST_B);
    STAGE(2 * ST_B);
    uint32_t offC = 0, offS = 3 * ST_B;

#pragma unroll 1
    for (int i = 0; i < 32; i++) {
        if (i <= 29) cp_wait2();
        else if (i == 30) cp_wait1();
        else cp_wait0();
        __syncthreads();
        if (i <= 28) STAGE(offS);
        COMPUTE(offC);
        offC += ST_B; if (offC == 4 * ST_B) offC = 0;
        offS += ST_B; if (offS == 4 * ST_B) offS = 0;
    }

    // epilogue: bias + GLU
    int r = lane >> 2;
    int c2 = (lane & 3) << 1;
    int h = hb * 64 + wm * 16 + r;
    float ba0 = bias[h],     bb0 = bias[h + HH];
    float ba8 = bias[h + 8], bb8 = bias[h + 8 + HH];
    size_t ob0 = ((size_t)b * HH + h) * LL;
    size_t ob8 = ob0 + (size_t)8 * LL;
#pragma unroll
    for (int t = 0; t < 8; t++) {
        int ll = lblk * 128 + wn * 64 + t * 8 + c2;
        float av, bv;
        float2 w0, w8;
        av = ca[t][0] + ba0; bv = cb[t][0] + bb0;
        w0.x = av * (1.0f / (1.0f + expf(-bv)));
        av = ca[t][1] + ba0; bv = cb[t][1] + bb0;
        w0.y = av * (1.0f / (1.0f + expf(-bv)));
        av = ca[t][2] + ba8; bv = cb[t][2] + bb8;
        w8.x = av * (1.0f / (1.0f + expf(-bv)));
        av = ca[t][3] + ba8; bv = cb[t][3] + bb8;
        w8.y = av * (1.0f / (1.0f + expf(-bv)));
        *(float2*)&out[ob0 + ll] = w0;
        *(float2*)&out[ob8 + ll] = w8;
    }
}

// ---------------------------------------------------------------------------
extern "C" void kernel_launch(void* const* d_in, const int* in_sizes, int n_in,
                              void* d_out, int out_size) {
    const float* x          = (const float*)d_in[0];
    const float* log_dt     = (const float*)d_in[1];
    const float* A_real_log = (const float*)d_in[2];
    const float* A_imag     = (const float*)d_in[3];
    const float* C_re       = (const float*)d_in[4];
    const float* C_im       = (const float*)d_in[5];
    const float* D          = (const float*)d_in[6];
    const float* W_out      = (const float*)d_in[7];
    const float* b_out      = (const float*)d_in[8];
    float* out = (float*)d_out;

    cudaFuncSetAttribute(gemm_glu_kernel, cudaFuncAttributeMaxDynamicSharedMemorySize,
                         GEMM_SMEM_BYTES);

    k_kernel<<<HH, 256>>>(log_dt, A_real_log, A_imag, C_re, C_im);
    wprep_kernel<<<(2 * HH * HH) / 1024, 256>>>(W_out);
    xprep_kernel<<<(int)(((size_t)BB * HH * LL) / 1024), 256>>>(x);
    tprep_kernel<<<HH, 256>>>();
    convgemm_kernel<<<dim3(2, HH), 256>>>(D);
    gemm_glu_kernel<<<dim3(2, 16, BB), 256, GEMM_SMEM_BYTES>>>(b_out, out);
}